// round 17
// baseline (speedup 1.0000x reference)
#include <cuda_runtime.h>
#include <cuda_bf16.h>
#include <cstdint>

// VectorQuant: N=8, S=2048, C=4, K=512, V=64
// R11-proven control flow: 128 CTAs (one wave), occ 1, TMEM alloc 512,
// both K-half MMAs up front to two mbarriers. bf16 inputs (example-verified
// idesc), f32 D: half h -> cols h*256. Group g (of 2) sweeps half g fully
// with 4x LDTM x64; score-in-place fp32, running-min, 64-bit candidate mask,
// exact-fp32 rescore from global (L2-hot). Combine over exactly 2 groups.
// SIMT fallback for the non-sm_103a compile pass.
// d_out layout: [out0: 8*2048*4*64][out1: 8*2048*4][out2: 8*2048*4]

#if defined(__CUDA_ARCH__) && (defined(__CUDA_ARCH_FEAT_SM103_ALL) || \
    (defined(__CUDA_ARCH_SPECIFIC__) && __CUDA_ARCH_SPECIFIC__ == 1030))
#define VQ_TC 1
#else
#define VQ_TC 0
#endif

#define NS     16384
#define CC     4
#define KK     512
#define VV     64
#define TPB    256
#define MTILE  128
#define TILES  4
#define MARGIN 1.0f

// byte offsets in dynamic smem
#define SB_B     0         // 65536: B bf16, two 32KB halves (256 rows x 128B), SW128
#define SB_A     65536     // 4 x 16384: A bf16 tiles (128 rows x 128B), SW128
#define SB_E2F   131072    // 512 floats: ||e_k||^2 exact fp32
#define SB_RED   133120    // 2 groups x 128 rows x 8B: (float d, int k)
#define SB_TPTR  135168    // tmem base ptr
#define SB_MBAR  135176    // 2 x 8B mbarriers
#define SB_TOTAL 135296

// idesc kind::f16 path, bf16 inputs, f32 D (matches test_2cta_mma_bf16 fields):
// dtype=F32 (1<<4), atype=BF16 (1<<7), btype=BF16 (1<<10), N=256, M=128.
static constexpr uint32_t IDESC_BF16 =
    (1u << 4) | (1u << 7) | (1u << 10) | ((256u / 8) << 17) | ((128u / 16) << 24);

static constexpr uint64_t DESC_BASE_SW128 =
    (uint64_t(2) << 61) | (uint64_t(1) << 46) | (uint64_t(64) << 32) | (uint64_t(1) << 16);

__device__ __forceinline__ uint32_t bf2_as_u(__nv_bfloat162 h) {
    union { __nv_bfloat162 h; uint32_t u; } v;
    v.h = h;
    return v.u;
}

__device__ __forceinline__ uint32_t smem_u32(const void* p) {
    uint32_t a;
    asm("{ .reg .u64 t; cvta.to.shared.u64 t, %1; cvt.u32.u64 %0, t; }" : "=r"(a) : "l"(p));
    return a;
}

// Swizzled byte offset of (row, vbyte) in an SW128 atom-blocked tile (vbyte < 128).
__device__ __forceinline__ uint32_t swz(int row, int vbyte) {
    uint32_t b = (uint32_t)((row >> 3) * 1024 + (row & 7) * 128 + vbyte);
    return b ^ ((b >> 3) & 0x70);
}

// Exact fp32 distance term from GLOBAL (L2-hot): e2[k] - 2 * x[row].e[k]
__device__ __forceinline__ float exact_d_g(const float4* xrow, const float* ec,
                                           float e2k, int k) {
    const float4* er = (const float4*)(ec + (size_t)k * VV);
    float d0 = 0.f, d1 = 0.f, d2 = 0.f, d3 = 0.f;
    #pragma unroll
    for (int v4 = 0; v4 < 16; v4++) {
        float4 xv = xrow[v4];
        float4 ev = er[v4];
        d0 = fmaf(xv.x, ev.x, d0);
        d1 = fmaf(xv.y, ev.y, d1);
        d2 = fmaf(xv.z, ev.z, d2);
        d3 = fmaf(xv.w, ev.w, d3);
    }
    return e2k - 2.0f * ((d0 + d1) + (d2 + d3));
}

__device__ __forceinline__ void upd_best(float d, int k, float& bd, int& bk) {
    if (d < bd || (d == bd && k < bk)) { bd = d; bk = k; }
}

#if VQ_TC
__device__ __forceinline__ uint32_t elect_one() {
    uint32_t pred;
    asm volatile("{\n\t.reg .pred p;\n\telect.sync _|p, 0xFFFFFFFF;\n\t"
                 "selp.b32 %0, 1, 0, p;\n\t}" : "=r"(pred));
    return pred;
}

__device__ __forceinline__ void mma_bf16_ss(uint32_t d_tmem, uint64_t a_desc,
                                            uint64_t b_desc, uint32_t idesc, bool en) {
    uint32_t e = en ? 1u : 0u;
    uint32_t z = 0u;
    asm volatile(
        "{\n\t.reg .pred p;\n\t"
        "setp.ne.u32 p, %5, 0;\n\t"
        "tcgen05.mma.cta_group::1.kind::f16 [%0], %1, %2, %3, {%4, %4, %4, %4}, p;\n\t}"
        :: "r"(d_tmem), "l"(a_desc), "l"(b_desc), "r"(idesc), "r"(z), "r"(e)
        : "memory");
}

#define LDTM_X64(r, addr)                                                     \
    asm volatile("tcgen05.ld.sync.aligned.32x32b.x64.b32 "                    \
        "{%0, %1, %2, %3, %4, %5, %6, %7, %8, %9, %10, %11, %12, %13, %14, %15, " \
        " %16, %17, %18, %19, %20, %21, %22, %23, %24, %25, %26, %27, %28, %29, %30, %31, " \
        " %32, %33, %34, %35, %36, %37, %38, %39, %40, %41, %42, %43, %44, %45, %46, %47, " \
        " %48, %49, %50, %51, %52, %53, %54, %55, %56, %57, %58, %59, %60, %61, %62, %63}, [%64];" \
        : "=r"((r)[0]),  "=r"((r)[1]),  "=r"((r)[2]),  "=r"((r)[3]),          \
          "=r"((r)[4]),  "=r"((r)[5]),  "=r"((r)[6]),  "=r"((r)[7]),          \
          "=r"((r)[8]),  "=r"((r)[9]),  "=r"((r)[10]), "=r"((r)[11]),         \
          "=r"((r)[12]), "=r"((r)[13]), "=r"((r)[14]), "=r"((r)[15]),         \
          "=r"((r)[16]), "=r"((r)[17]), "=r"((r)[18]), "=r"((r)[19]),         \
          "=r"((r)[20]), "=r"((r)[21]), "=r"((r)[22]), "=r"((r)[23]),         \
          "=r"((r)[24]), "=r"((r)[25]), "=r"((r)[26]), "=r"((r)[27]),         \
          "=r"((r)[28]), "=r"((r)[29]), "=r"((r)[30]), "=r"((r)[31]),         \
          "=r"((r)[32]), "=r"((r)[33]), "=r"((r)[34]), "=r"((r)[35]),         \
          "=r"((r)[36]), "=r"((r)[37]), "=r"((r)[38]), "=r"((r)[39]),         \
          "=r"((r)[40]), "=r"((r)[41]), "=r"((r)[42]), "=r"((r)[43]),         \
          "=r"((r)[44]), "=r"((r)[45]), "=r"((r)[46]), "=r"((r)[47]),         \
          "=r"((r)[48]), "=r"((r)[49]), "=r"((r)[50]), "=r"((r)[51]),         \
          "=r"((r)[52]), "=r"((r)[53]), "=r"((r)[54]), "=r"((r)[55]),         \
          "=r"((r)[56]), "=r"((r)[57]), "=r"((r)[58]), "=r"((r)[59]),         \
          "=r"((r)[60]), "=r"((r)[61]), "=r"((r)[62]), "=r"((r)[63])          \
        : "r"(addr))

__device__ __forceinline__ void mbar_wait_parity(uint32_t mbar, uint32_t parity) {
    uint32_t done;
    asm volatile(
        "{\n\t.reg .pred p;\n\t"
        "mbarrier.try_wait.parity.acquire.cta.shared::cta.b64 p, [%1], %2;\n\t"
        "selp.b32 %0, 1, 0, p;\n\t}"
        : "=r"(done) : "r"(mbar), "r"(parity) : "memory");
    if (!done) {
        asm volatile(
            "{\n\t.reg .pred P1;\n\t"
            "WAIT_LOOP_%=:\n\t"
            "mbarrier.try_wait.parity.acquire.cta.shared::cta.b64 P1, [%0], %1, 0x989680;\n\t"
            "@P1 bra.uni WAIT_DONE_%=;\n\t"
            "bra.uni WAIT_LOOP_%=;\n\t"
            "WAIT_DONE_%=:\n\t}"
            :: "r"(mbar), "r"(parity) : "memory");
    }
}
#endif  // VQ_TC

extern __shared__ __align__(1024) float smem_dyn[];

__global__ void __launch_bounds__(TPB, 1)
vq_tc_kernel(const float* __restrict__ x, const float* __restrict__ emb,
             float* __restrict__ out0, float* __restrict__ out1,
             float* __restrict__ out2)
{
    char* smem = (char*)smem_dyn;
    const uint32_t smem_base = smem_u32(smem);
    float* e2f = (float*)(smem + SB_E2F);
    const int tid = threadIdx.x;
    const int wid = tid >> 5;
    const int lid = tid & 31;
    const int w   = wid & 3;       // TMEM lane partition
    const int g   = wid >> 2;      // K-half: k in [g*256, g*256+256)
    const int row = w * 32 + lid;  // row owned in sweep

    const int c  = blockIdx.y;
    const float* ec = emb + (size_t)c * KK * VV;
    const int tile0 = blockIdx.x * TILES;

#if VQ_TC
    const uint32_t mbar0 = smem_base + SB_MBAR;
    if (wid == 0) {
        asm volatile("tcgen05.alloc.cta_group::1.sync.aligned.shared::cta.b32 [%0], %1;"
                     :: "r"(smem_base + SB_TPTR), "r"(512u) : "memory");
        asm volatile("tcgen05.relinquish_alloc_permit.cta_group::1.sync.aligned;");
    }
    if (tid == 0) {
        asm volatile("mbarrier.init.shared.b64 [%0], %1;" :: "r"(mbar0), "r"(1u) : "memory");
        asm volatile("mbarrier.init.shared.b64 [%0], %1;" :: "r"(mbar0 + 8), "r"(1u) : "memory");
    }
#endif

    // ---- Setup: B (512x64 fp32) -> bf16 in two 32KB SW128 halves ----
    {
        const float4* ec4 = (const float4*)ec;
        for (int it = 0; it < 16; it++) {
            int idx = it * TPB + tid;          // 0..4095 chunks of 8 bf16
            int k = idx >> 3;
            int j = idx & 7;                   // 16B chunk within the 128B row
            float4 a = ec4[k * 16 + j * 2];
            float4 b = ec4[k * 16 + j * 2 + 1];
            uint4 o;
            o.x = bf2_as_u(__floats2bfloat162_rn(a.x, a.y));
            o.y = bf2_as_u(__floats2bfloat162_rn(a.z, a.w));
            o.z = bf2_as_u(__floats2bfloat162_rn(b.x, b.y));
            o.w = bf2_as_u(__floats2bfloat162_rn(b.z, b.w));
            uint32_t off = SB_B + (k >> 8) * 32768 + swz(k & 255, j * 16);
            *(uint4*)(smem + off) = o;
        }
    }
    // ---- Setup: A tiles (4 x 128x64 fp32) -> bf16 ----
    {
        for (int it = 0; it < 16; it++) {
            int idx = it * TPB + tid;          // 0..4095
            int t = idx >> 10;                 // tile 0..3
            int r = (idx >> 3) & 127;
            int j = idx & 7;
            const float4* xp = (const float4*)(x +
                ((size_t)((tile0 + t) * MTILE + r) * CC + c) * VV);
            float4 a = xp[j * 2];
            float4 b = xp[j * 2 + 1];
            uint4 o;
            o.x = bf2_as_u(__floats2bfloat162_rn(a.x, a.y));
            o.y = bf2_as_u(__floats2bfloat162_rn(a.z, a.w));
            o.z = bf2_as_u(__floats2bfloat162_rn(b.x, b.y));
            o.w = bf2_as_u(__floats2bfloat162_rn(b.z, b.w));
            uint32_t off = SB_A + t * 16384 + swz(r, j * 16);
            *(uint4*)(smem + off) = o;
        }
    }
    // ---- e2[k] exact fp32 (2 per thread) ----
    #pragma unroll
    for (int p = 0; p < 2; p++) {
        int k = tid * 2 + p;
        const float4* rp = (const float4*)(ec + (size_t)k * VV);
        float s = 0.f;
        #pragma unroll
        for (int i = 0; i < VV / 4; i++) {
            float4 v = rp[i];
            s += v.x * v.x + v.y * v.y + v.z * v.z + v.w * v.w;
        }
        e2f[k] = s;
    }

    asm volatile("fence.proxy.async.shared::cta;" ::: "memory");
    __syncthreads();

#if VQ_TC
    uint32_t tmem_base;
    asm volatile("ld.shared.b32 %0, [%1];" : "=r"(tmem_base) : "r"(smem_base + SB_TPTR));
#endif

    for (int t = 0; t < TILES; t++) {
        const int rglob0 = (tile0 + t) * MTILE;
        float bd = 3.4e38f;
        int bk = 1 << 30;
        const float4* xrow = (const float4*)(x + ((size_t)(rglob0 + row) * CC + c) * VV);

#if VQ_TC
        // ---- MMA: D[128,512] (f32) = A.B^T, half h -> cols h*256, own mbar ----
        if (wid == 0 && elect_one()) {
            const uint64_t a_base = DESC_BASE_SW128 |
                (((smem_base + SB_A + t * 16384) >> 4) & 0x3FFF);
            #pragma unroll
            for (int h = 0; h < 2; h++) {
                const uint64_t b_base = DESC_BASE_SW128 |
                    (((smem_base + SB_B + h * 32768) >> 4) & 0x3FFF);
                #pragma unroll
                for (int s = 0; s < 4; s++) {   // K=64 bf16, 16 per MMA step
                    mma_bf16_ss(tmem_base + h * 256, a_base + 2 * s, b_base + 2 * s,
                                IDESC_BF16, s > 0);
                }
                asm volatile(
                    "tcgen05.commit.cta_group::1.mbarrier::arrive::one.shared::cluster.b64 [%0];"
                    :: "r"(mbar0 + 8u * h) : "memory");
            }
        }

        mbar_wait_parity(mbar0 + 8u * g, (uint32_t)(t & 1));
        asm volatile("tcgen05.fence::after_thread_sync;" ::: "memory");

        // ---- Sweep half g: 4 chunks of 64 cols via LDTM x64 ----
        float runmin = 3.4e38f;
        #pragma unroll 1
        for (int j = 0; j < 4; j++) {
            uint32_t r32[64];
            LDTM_X64(r32, tmem_base + g * 256 + j * 64);
            asm volatile("tcgen05.wait::ld.sync.aligned;" ::: "memory");
            const int kbase = g * 256 + j * 64;
            const float4* e2v = (const float4*)(e2f + kbase);
            // score in place + chunk min
            float m0 = 3.4e38f, m1 = 3.4e38f, m2 = 3.4e38f, m3 = 3.4e38f;
            #pragma unroll
            for (int i4 = 0; i4 < 16; i4++) {
                float4 ev = e2v[i4];
                float s0 = fmaf(-2.0f, __uint_as_float(r32[i4 * 4]),     ev.x);
                float s1 = fmaf(-2.0f, __uint_as_float(r32[i4 * 4 + 1]), ev.y);
                float s2 = fmaf(-2.0f, __uint_as_float(r32[i4 * 4 + 2]), ev.z);
                float s3 = fmaf(-2.0f, __uint_as_float(r32[i4 * 4 + 3]), ev.w);
                r32[i4 * 4]     = __float_as_uint(s0);
                r32[i4 * 4 + 1] = __float_as_uint(s1);
                r32[i4 * 4 + 2] = __float_as_uint(s2);
                r32[i4 * 4 + 3] = __float_as_uint(s3);
                m0 = fminf(m0, s0);
                m1 = fminf(m1, s1);
                m2 = fminf(m2, s2);
                m3 = fminf(m3, s3);
            }
            runmin = fminf(runmin, fminf(fminf(m0, m1), fminf(m2, m3)));
            const float thr = runmin + MARGIN;
            // candidate bitmasks (superset w.r.t. final thr)
            uint32_t mlo = 0u, mhi = 0u;
            #pragma unroll
            for (int i = 0; i < 32; i++) {
                if (__uint_as_float(r32[i]) < thr) mlo |= (1u << i);
                if (__uint_as_float(r32[32 + i]) < thr) mhi |= (1u << i);
            }
            while (mlo) {
                int i = __ffs(mlo) - 1;
                mlo &= mlo - 1;
                int k = kbase + i;
                upd_best(exact_d_g(xrow, ec, e2f[k], k), k, bd, bk);
            }
            while (mhi) {
                int i = __ffs(mhi) - 1;
                mhi &= mhi - 1;
                int k = kbase + 32 + i;
                upd_best(exact_d_g(xrow, ec, e2f[k], k), k, bd, bk);
            }
        }
        asm volatile("tcgen05.fence::before_thread_sync;" ::: "memory");
#else
        // ---- SIMT fallback: exact scan of this (g,row)'s 256 codes ----
        for (int kk = 0; kk < 256; kk++) {
            int k = g * 256 + kk;
            upd_best(exact_d_g(xrow, ec, e2f[k], k), k, bd, bk);
        }
#endif

        *(float*)(smem + SB_RED + (g * MTILE + row) * 8) = bd;
        *(int*)(smem + SB_RED + (g * MTILE + row) * 8 + 4) = bk;
        __syncthreads();

        // ---- Combine the TWO groups + epilogue: 2 threads/row, fp32 global ----
        {
            const int rw = tid >> 1;       // row 0..127
            const int half = tid & 1;      // 32-element half of the vector
            float d0v = *(float*)(smem + SB_RED + rw * 8);
            int k0v = *(int*)(smem + SB_RED + rw * 8 + 4);
            float d1v = *(float*)(smem + SB_RED + (MTILE + rw) * 8);
            int k1v = *(int*)(smem + SB_RED + (MTILE + rw) * 8 + 4);
            upd_best(d1v, k1v, d0v, k0v);
            const int bkr = k0v;

            const int rglob = rglob0 + rw;
            const float4* xr = (const float4*)(x + ((size_t)rglob * CC + c) * VV) + half * 8;
            const float4* er = (const float4*)(ec + (size_t)bkr * VV) + half * 8;
            float4* o0 = (float4*)(out0 + ((size_t)rglob * CC + c) * VV) + half * 8;
            float ss = 0.f;
            #pragma unroll
            for (int i = 0; i < 8; i++) {
                float4 xv = xr[i];
                float4 ev = er[i];
                float q0 = xv.x - ev.x;
                float q1 = xv.y - ev.y;
                float q2 = xv.z - ev.z;
                float q3 = xv.w - ev.w;
                ss += q0 * q0 + q1 * q1 + q2 * q2 + q3 * q3;
                o0[i] = ev;
            }
            ss += __shfl_xor_sync(0xffffffffu, ss, 1);
            if (half == 0) {
                out1[(size_t)rglob * CC + c] = ss;
                out2[(size_t)rglob * CC + c] = ss;
            }
        }
        __syncthreads();
    }

#if VQ_TC
    if (wid == 0) {
        asm volatile("tcgen05.dealloc.cta_group::1.sync.aligned.b32 %0, %1;"
                     :: "r"(tmem_base), "r"(512u));
    }
#endif
}

extern "C" void kernel_launch(void* const* d_in, const int* in_sizes, int n_in,
                              void* d_out, int out_size) {
    const float* x   = (const float*)d_in[0];
    const float* emb = (const float*)d_in[1];
    float* out  = (float*)d_out;
    float* out0 = out;
    float* out1 = out + (size_t)NS * CC * VV;
    float* out2 = out1 + (size_t)NS * CC;

    cudaFuncSetAttribute(vq_tc_kernel, cudaFuncAttributeMaxDynamicSharedMemorySize,
                         SB_TOTAL);
    dim3 grid(NS / (MTILE * TILES), CC);
    vq_tc_kernel<<<grid, TPB, SB_TOTAL>>>(x, emb, out0, out1, out2);
}